// round 6
// baseline (speedup 1.0000x reference)
#include <cuda_runtime.h>
#include <cuda_fp16.h>

#define N_NODES 49998
#define E_EDGES 800000
#define HH0 8
#define DIN 128
#define DOUT 32
#define F0DIM (HH0*DOUT)   /* 256 */

typedef unsigned long long ull;

// -------- scratch (device globals; no allocation allowed) --------
__device__ __half g_f0h[N_NODES*F0DIM];   // fp16 gather copy of layer-0 features
__device__ float  g_h0 [N_NODES*F0DIM];
__device__ float  g_el0[N_NODES*HH0];
__device__ float  g_er0[N_NODES*HH0];
__device__ __half g_f1h[N_NODES*DOUT];    // fp16 gather copy of layer-1 features
__device__ float  g_h1 [N_NODES*DOUT];
__device__ float  g_el1[N_NODES];
__device__ float  g_er1[N_NODES];
__device__ int    g_deg[N_NODES];
__device__ int    g_cursor[N_NODES];
__device__ int    g_rowptr[N_NODES+1];
__device__ int    g_csr_src[E_EDGES];

__device__ __forceinline__ float lrelu02(float v) { return v > 0.f ? v : 0.2f * v; }

// ---- packed fp32x2 helpers (exact fp32 semantics, 2x FFMA issue density) ----
__device__ __forceinline__ ull fma2(ull a, ull b, ull c) {
    ull d;
    asm("fma.rn.f32x2 %0, %1, %2, %3;" : "=l"(d) : "l"(a), "l"(b), "l"(c));
    return d;
}
__device__ __forceinline__ ull pack2(float a, float b) {
    ull r;
    asm("mov.b64 %0, {%1, %2};" : "=l"(r) : "r"(__float_as_uint(a)), "r"(__float_as_uint(b)));
    return r;
}
__device__ __forceinline__ ull dup2(float a) {
    ull r;
    asm("mov.b64 %0, {%1, %1};" : "=l"(r) : "r"(__float_as_uint(a)));
    return r;
}
__device__ __forceinline__ float2 unpack2(ull v) {
    unsigned lo, hi;
    asm("mov.b64 {%0, %1}, %2;" : "=r"(lo), "=r"(hi) : "l"(v));
    return make_float2(__uint_as_float(lo), __uint_as_float(hi));
}
__device__ __forceinline__ ull h2f2(__half2 h) {
    float2 f = __half22float2(h);
    return pack2(f.x, f.y);
}

// ================= CSR build =================
__global__ void hist_k(const int* __restrict__ dst, int E) {
    int e = blockIdx.x * blockDim.x + threadIdx.x;
    if (e < E) atomicAdd(&g_deg[dst[e]], 1);
}
// single-block fused scan: deg -> rowptr (exclusive) + cursor
__global__ void scan_fused_k(int n, int E) {
    __shared__ int tot[1024];
    int t = threadIdx.x;
    int per = (n + 1023) / 1024;
    int lo = min(t * per, n), hi = min(lo + per, n);
    int sum = 0;
    for (int i = lo; i < hi; i++) sum += g_deg[i];
    tot[t] = sum;
    __syncthreads();
    #pragma unroll
    for (int off = 1; off < 1024; off <<= 1) {
        int v = (t >= off) ? tot[t - off] : 0;
        __syncthreads();
        tot[t] += v;
        __syncthreads();
    }
    int run = tot[t] - sum;   // exclusive chunk offset
    for (int i = lo; i < hi; i++) {
        g_rowptr[i] = run;
        g_cursor[i] = run;
        run += g_deg[i];
    }
    if (t == 0) g_rowptr[n] = E;
}
__global__ void fill_k(const int* __restrict__ src, const int* __restrict__ dst, int E) {
    int e = blockIdx.x * blockDim.x + threadIdx.x;
    if (e >= E) return;
    int d = dst[e];
    int pos = atomicAdd(&g_cursor[d], 1);
    g_csr_src[pos] = src[e];
}

// ================= layer-0 GEMM: f0 = x @ W0 (stored fp16), el0/er0 =================
// grid (ceil(n/64), 4). block 128. thread tile: 4 nodes x 8 cols.
#define XS_STRIDE 129
__global__ void __launch_bounds__(128) gemm0_k(
        const float* __restrict__ x, const float* __restrict__ W0,
        const float* __restrict__ al0, const float* __restrict__ ar0, int n) {
    __shared__ float xs[64 * XS_STRIDE];
    __shared__ float s_el[64][2];
    __shared__ float s_er[64][2];
    int t  = threadIdx.x;
    int n0 = blockIdx.x * 64;
    int j0 = blockIdx.y * 64;

    for (int i = t; i < 64 * 32; i += 128) {
        int r = i >> 5, c4 = i & 31;
        int node = n0 + r;
        float4 v = make_float4(0.f, 0.f, 0.f, 0.f);
        if (node < n) v = *(const float4*)&x[node * DIN + c4 * 4];
        float* xp = &xs[r * XS_STRIDE + c4 * 4];
        xp[0] = v.x; xp[1] = v.y; xp[2] = v.z; xp[3] = v.w;
    }
    if (t < 64) { s_el[t][0] = 0.f; s_el[t][1] = 0.f; s_er[t][0] = 0.f; s_er[t][1] = 0.f; }
    __syncthreads();

    int tn = t & 15, tc = t >> 4;
    int jb = j0 + tc * 8;

    ull acc[8][2];
    #pragma unroll
    for (int j = 0; j < 8; j++) { acc[j][0] = 0ull; acc[j][1] = 0ull; }

    const float* xr0 = &xs[(tn     ) * XS_STRIDE];
    const float* xr1 = &xs[(tn + 16) * XS_STRIDE];
    const float* xr2 = &xs[(tn + 32) * XS_STRIDE];
    const float* xr3 = &xs[(tn + 48) * XS_STRIDE];

    #pragma unroll 4
    for (int k = 0; k < DIN; k++) {
        ull xa = pack2(xr0[k], xr1[k]);
        ull xb = pack2(xr2[k], xr3[k]);
        const float4* wp = (const float4*)&W0[k * F0DIM + jb];
        float4 w0 = wp[0], w1 = wp[1];
        float wv[8] = {w0.x, w0.y, w0.z, w0.w, w1.x, w1.y, w1.z, w1.w};
        #pragma unroll
        for (int j = 0; j < 8; j++) {
            ull w2 = dup2(wv[j]);
            acc[j][0] = fma2(xa, w2, acc[j][0]);
            acc[j][1] = fma2(xb, w2, acc[j][1]);
        }
    }

    float f[4][8];
    #pragma unroll
    for (int j = 0; j < 8; j++) {
        float2 a = unpack2(acc[j][0]);
        float2 b = unpack2(acc[j][1]);
        f[0][j] = a.x; f[1][j] = a.y; f[2][j] = b.x; f[3][j] = b.y;
    }
    float pl[4] = {0.f,0.f,0.f,0.f}, pr[4] = {0.f,0.f,0.f,0.f};
    #pragma unroll
    for (int j = 0; j < 8; j++) {
        float alv = al0[jb + j], arv = ar0[jb + j];
        #pragma unroll
        for (int i = 0; i < 4; i++) {
            pl[i] = fmaf(f[i][j], alv, pl[i]);
            pr[i] = fmaf(f[i][j], arv, pr[i]);
        }
    }
    int hl = tc >> 2;
    #pragma unroll
    for (int i = 0; i < 4; i++) {
        int rloc = tn + 16 * i;
        int node = n0 + rloc;
        if (node < n) {
            __half2 h0 = __floats2half2_rn(f[i][0], f[i][1]);
            __half2 h1 = __floats2half2_rn(f[i][2], f[i][3]);
            __half2 h2 = __floats2half2_rn(f[i][4], f[i][5]);
            __half2 h3 = __floats2half2_rn(f[i][6], f[i][7]);
            uint4 packed;
            packed.x = *(unsigned*)&h0; packed.y = *(unsigned*)&h1;
            packed.z = *(unsigned*)&h2; packed.w = *(unsigned*)&h3;
            *(uint4*)&g_f0h[(size_t)node * F0DIM + jb] = packed;
            atomicAdd(&s_el[rloc][hl], pl[i]);
            atomicAdd(&s_er[rloc][hl], pr[i]);
        }
    }
    __syncthreads();
    {
        int r = t >> 1, h2 = t & 1;
        int node = n0 + r;
        if (node < n) {
            g_el0[node * HH0 + blockIdx.y * 2 + h2] = s_el[r][h2];
            g_er0[node * HH0 + blockIdx.y * 2 + h2] = s_er[r][h2];
        }
    }
}

// ================= layer-0 fused softmax + gather + bias + ELU =================
// warp per dst node; lane l owns cols 8l..8l+7 (head h = l>>2); fp16 gather.
__global__ void __launch_bounds__(256) agg0_k(const float* __restrict__ b0, int n) {
    int t = threadIdx.x, l = t & 31;
    int d = blockIdx.x * 8 + (t >> 5);
    if (d >= n) return;
    int row0 = g_rowptr[d], row1 = g_rowptr[d + 1];
    int h = l >> 2;
    float er = g_er0[d * HH0 + h];

    ull acc[4] = {0ull, 0ull, 0ull, 0ull};
    float den = 0.f;

    #pragma unroll 2
    for (int e = row0; e < row1; e++) {
        int s = __ldg(&g_csr_src[e]);
        float w = __expf(lrelu02(__ldg(&g_el0[s * HH0 + h]) + er));
        den += w;
        ull w2 = dup2(w);
        uint4 v = __ldg((const uint4*)&g_f0h[(size_t)s * F0DIM + 8 * l]);
        acc[0] = fma2(h2f2(*(__half2*)&v.x), w2, acc[0]);
        acc[1] = fma2(h2f2(*(__half2*)&v.y), w2, acc[1]);
        acc[2] = fma2(h2f2(*(__half2*)&v.z), w2, acc[2]);
        acc[3] = fma2(h2f2(*(__half2*)&v.w), w2, acc[3]);
    }

    float inv = (row1 > row0) ? 1.f / den : 0.f;
    const float4* bp = (const float4*)&b0[8 * l];
    float4 ba = bp[0], bb = bp[1];
    float o[8];
    float2 u0 = unpack2(acc[0]), u1 = unpack2(acc[1]);
    float2 u2 = unpack2(acc[2]), u3 = unpack2(acc[3]);
    o[0] = u0.x * inv + ba.x; o[1] = u0.y * inv + ba.y;
    o[2] = u1.x * inv + ba.z; o[3] = u1.y * inv + ba.w;
    o[4] = u2.x * inv + bb.x; o[5] = u2.y * inv + bb.y;
    o[6] = u3.x * inv + bb.z; o[7] = u3.y * inv + bb.w;
    #pragma unroll
    for (int i = 0; i < 8; i++) o[i] = o[i] > 0.f ? o[i] : expm1f(o[i]);   // ELU
    float* dst = &g_h0[(size_t)d * F0DIM + 8 * l];
    *(float4*)dst       = make_float4(o[0], o[1], o[2], o[3]);
    *(float4*)(dst + 4) = make_float4(o[4], o[5], o[6], o[7]);
}

// ================= layer-1 GEMM: f1 = h0 @ W1 (stored fp16), el1/er1 =================
__global__ void __launch_bounds__(128) gemm1_k(
        const float* __restrict__ W1,
        const float* __restrict__ al1, const float* __restrict__ ar1, int n) {
    __shared__ float hs[64 * XS_STRIDE];
    __shared__ float s_el[64];
    __shared__ float s_er[64];
    int t  = threadIdx.x;
    int n0 = blockIdx.x * 64;
    int tn = t & 15, tc = t >> 4;
    int jb = tc * 4;

    if (t < 64) { s_el[t] = 0.f; s_er[t] = 0.f; }

    ull acc[4][2];
    #pragma unroll
    for (int j = 0; j < 4; j++) { acc[j][0] = 0ull; acc[j][1] = 0ull; }

    const float* hr0 = &hs[(tn     ) * XS_STRIDE];
    const float* hr1 = &hs[(tn + 16) * XS_STRIDE];
    const float* hr2 = &hs[(tn + 32) * XS_STRIDE];
    const float* hr3 = &hs[(tn + 48) * XS_STRIDE];

    for (int c = 0; c < 2; c++) {
        __syncthreads();
        for (int i = t; i < 64 * 32; i += 128) {
            int r = i >> 5, c4 = i & 31;
            int node = n0 + r;
            float4 v = make_float4(0.f, 0.f, 0.f, 0.f);
            if (node < n) v = *(const float4*)&g_h0[(size_t)node * F0DIM + c * 128 + c4 * 4];
            float* hp = &hs[r * XS_STRIDE + c4 * 4];
            hp[0] = v.x; hp[1] = v.y; hp[2] = v.z; hp[3] = v.w;
        }
        __syncthreads();
        #pragma unroll 4
        for (int k = 0; k < 128; k++) {
            ull xa = pack2(hr0[k], hr1[k]);
            ull xb = pack2(hr2[k], hr3[k]);
            float4 w = *(const float4*)&W1[(c * 128 + k) * DOUT + jb];
            float wv[4] = {w.x, w.y, w.z, w.w};
            #pragma unroll
            for (int j = 0; j < 4; j++) {
                ull w2 = dup2(wv[j]);
                acc[j][0] = fma2(xa, w2, acc[j][0]);
                acc[j][1] = fma2(xb, w2, acc[j][1]);
            }
        }
    }

    float f[4][4];
    #pragma unroll
    for (int j = 0; j < 4; j++) {
        float2 a = unpack2(acc[j][0]);
        float2 b = unpack2(acc[j][1]);
        f[0][j] = a.x; f[1][j] = a.y; f[2][j] = b.x; f[3][j] = b.y;
    }
    float pl[4] = {0.f,0.f,0.f,0.f}, pr[4] = {0.f,0.f,0.f,0.f};
    #pragma unroll
    for (int j = 0; j < 4; j++) {
        float alv = al1[jb + j], arv = ar1[jb + j];
        #pragma unroll
        for (int i = 0; i < 4; i++) {
            pl[i] = fmaf(f[i][j], alv, pl[i]);
            pr[i] = fmaf(f[i][j], arv, pr[i]);
        }
    }
    #pragma unroll
    for (int i = 0; i < 4; i++) {
        int rloc = tn + 16 * i;
        int node = n0 + rloc;
        if (node < n) {
            __half2 h0 = __floats2half2_rn(f[i][0], f[i][1]);
            __half2 h1 = __floats2half2_rn(f[i][2], f[i][3]);
            uint2 packed;
            packed.x = *(unsigned*)&h0; packed.y = *(unsigned*)&h1;
            *(uint2*)&g_f1h[(size_t)node * DOUT + jb] = packed;
            atomicAdd(&s_el[rloc], pl[i]);
            atomicAdd(&s_er[rloc], pr[i]);
        }
    }
    __syncthreads();
    if (t < 64) {
        int node = n0 + t;
        if (node < n) { g_el1[node] = s_el[t]; g_er1[node] = s_er[t]; }
    }
}

// ================= layer-1 fused softmax + gather + bias =================
__global__ void __launch_bounds__(256) agg1_k(const float* __restrict__ b1, int n) {
    int t = threadIdx.x, lane = t & 31;
    int node = blockIdx.x * 8 + (t >> 5);
    if (node >= n) return;
    int row0 = g_rowptr[node], row1 = g_rowptr[node + 1];
    float er = g_er1[node];
    float acc = 0.f, den = 0.f;
    #pragma unroll 2
    for (int e = row0; e < row1; e++) {
        int s = __ldg(&g_csr_src[e]);
        float w = __expf(lrelu02(__ldg(&g_el1[s]) + er));
        den += w;
        acc = fmaf(w, __half2float(__ldg(&g_f1h[(size_t)s * DOUT + lane])), acc);
    }
    float o = (row1 > row0) ? acc / den : 0.f;
    g_h1[(size_t)node * DOUT + lane] = o + b1[lane];
}

// ================= link predictor =================
__global__ void predictor_k(const float* __restrict__ P1, const float* __restrict__ pb1,
                            const float* __restrict__ P2, const float* __restrict__ pb2,
                            const float* __restrict__ P3, const float* __restrict__ pb3,
                            float* __restrict__ out, int num_edge) {
    int w = (blockIdx.x * blockDim.x + threadIdx.x) >> 5;
    int lane = threadIdx.x & 31;
    if (w >= 2 * num_edge) return;
    int branch = w / num_edge;
    int i = w - branch * num_edge;
    const float* a = g_h1 + (size_t)i * DOUT;
    const float* b = g_h1 + (size_t)(num_edge * (1 + branch) + i) * DOUT;
    float z = a[lane] * b[lane];

    float acc = pb1[lane];
    #pragma unroll
    for (int k = 0; k < 32; k++)
        acc = fmaf(__shfl_sync(0xffffffffu, z, k), P1[k * 32 + lane], acc);
    z = fmaxf(acc, 0.f);

    acc = pb2[lane];
    #pragma unroll
    for (int k = 0; k < 32; k++)
        acc = fmaf(__shfl_sync(0xffffffffu, z, k), P2[k * 32 + lane], acc);
    z = fmaxf(acc, 0.f);

    float p = z * P3[lane];
    #pragma unroll
    for (int off = 16; off; off >>= 1) p += __shfl_xor_sync(0xffffffffu, p, off);
    if (lane == 0) out[branch * num_edge + i] = p + pb3[0];
}

// ================= launch =================
extern "C" void kernel_launch(void* const* d_in, const int* in_sizes, int n_in,
                              void* d_out, int out_size) {
    const float* x   = (const float*)d_in[0];
    const int*   src = (const int*)  d_in[1];
    const int*   dst = (const int*)  d_in[2];
    const float* W0  = (const float*)d_in[4];
    const float* al0 = (const float*)d_in[5];
    const float* ar0 = (const float*)d_in[6];
    const float* b0  = (const float*)d_in[7];
    const float* W1  = (const float*)d_in[8];
    const float* al1 = (const float*)d_in[9];
    const float* ar1 = (const float*)d_in[10];
    const float* b1  = (const float*)d_in[11];
    const float* P1  = (const float*)d_in[12];
    const float* pb1 = (const float*)d_in[13];
    const float* P2  = (const float*)d_in[14];
    const float* pb2 = (const float*)d_in[15];
    const float* P3  = (const float*)d_in[16];
    const float* pb3 = (const float*)d_in[17];
    float* out = (float*)d_out;

    int n = in_sizes[0] / DIN;   // 49998
    int E = in_sizes[1];         // 800000
    int num_edge = n / 3;        // neg_sample_ratio = 1

    void* p_deg;
    cudaGetSymbolAddress(&p_deg, g_deg);

    const int T = 256;
    // ---- CSR build (by dst): memset + hist + fused scan + fill ----
    cudaMemsetAsync(p_deg, 0, (size_t)n * sizeof(int));
    hist_k<<<(E + T - 1) / T, T>>>(dst, E);
    scan_fused_k<<<1, 1024>>>(n, E);
    fill_k<<<(E + T - 1) / T, T>>>(src, dst, E);
    // ---- layer 0 ----
    gemm0_k<<<dim3((n + 63) / 64, 4), 128>>>(x, W0, al0, ar0, n);
    agg0_k<<<(n + 7) / 8, T>>>(b0, n);
    // ---- layer 1 ----
    gemm1_k<<<(n + 63) / 64, 128>>>(W1, al1, ar1, n);
    agg1_k<<<(n + 7) / 8, T>>>(b1, n);
    // ---- predictor ----
    predictor_k<<<(2 * num_edge * 32 + T - 1) / T, T>>>(P1, pb1, P2, pb2, P3, pb3, out, num_edge);
}